// round 9
// baseline (speedup 1.0000x reference)
#include <cuda_runtime.h>
#include <math.h>

#define BB 32
#define CC 256
#define HH 96
#define WW 96
#define CR 64
#define PITCH 96

// Scratch (no allocs allowed)
__device__ float g_pooled[BB*9*CC];     // [b][p][c] block sums
__device__ float g_weight[BB*9*CC];     // [b][p][c]
__device__ float g_bias[BB*CC];
__device__ float g_w1t[CC*CR];          // [k][o], BN inv folded
__device__ float g_w2t[CR*2*CC];        // [k][n]
__device__ float g_bnb[CR];
__device__ float g_dwt[2*9*CC];         // [g][p][c]
__device__ unsigned g_cnt[BB];          // contributions (256/sample/run, never reset)
__device__ unsigned g_done[BB];         // proj completions (1/sample/run)
__device__ unsigned g_prep;             // prep completions (114/run)

__global__ __launch_bounds__(288, 5) void fused_kernel(
    const float* __restrict__ x,
    const float* __restrict__ dyn_weight,
    const float* __restrict__ dyn_bias,
    const float* __restrict__ w1,
    const float* __restrict__ bn_gamma,
    const float* __restrict__ bn_beta,
    const float* __restrict__ bn_mean,
    const float* __restrict__ bn_var,
    const float* __restrict__ w2,
    const float* __restrict__ b2,
    float* __restrict__ y)
{
    __shared__ float tile[98 * PITCH];
    __shared__ float sh[640];
    __shared__ float sgap[CC];
    __shared__ unsigned s_ret;

    int bc = blockIdx.x, t = threadIdx.x;
    int b = bc >> 8, c = bc & 255;
    const float* img = x + (size_t)bc * (HH*WW);
    float* outimg = y + (size_t)bc * (HH*WW);

    // zero halo rows 0 and 97
    float4 z4 = make_float4(0.f,0.f,0.f,0.f);
    if (t < 24) {
        *reinterpret_cast<float4*>(&tile[t * 4]) = z4;
    } else if (t < 48) {
        *reinterpret_cast<float4*>(&tile[97 * PITCH + (t - 24) * 4]) = z4;
    }

    // stage image: 2304 x 16B cp.async
#pragma unroll
    for (int i = 0; i < 8; i++) {
        int idx = t + i * 288;
        int r = idx / 24, j = idx % 24;
        unsigned sa = (unsigned)__cvta_generic_to_shared(&tile[(r + 1) * PITCH + j * 4]);
        asm volatile("cp.async.cg.shared.global [%0], [%1], 16;\n"
                     :: "r"(sa), "l"(img + r * WW + j * 4));
    }
    asm volatile("cp.async.commit_group;\n");

    // prep (overlapped with DMA): 114*288 = 32832 >= 32768 items
    if (bc < 114) {
        int idx = bc * 288 + t;
        if (idx < CC*CR) {
            int k = idx >> 6, o = idx & 63;
            float inv = bn_gamma[o] * rsqrtf(bn_var[o] + 1e-5f);
            g_w1t[idx] = w1[o * CC + k] * inv;
        }
        if (idx < CR*2*CC) {
            int k = idx >> 9, n = idx & 511;
            g_w2t[idx] = w2[n * CR + k];
        }
        if (idx < 2*9*CC) {
            int g = idx / (9*CC);
            int rem = idx - g * 9 * CC;
            int p = rem >> 8, c2 = rem & 255;
            g_dwt[idx] = dyn_weight[(g * CC + c2) * 9 + p];
        }
        if (idx < CR) {
            float inv = bn_gamma[idx] * rsqrtf(bn_var[idx] + 1e-5f);
            g_bnb[idx] = bn_beta[idx] - bn_mean[idx] * inv;
        }
        __threadfence();
        __syncthreads();
        if (t == 0) atomicAdd(&g_prep, 1u);
    }

    asm volatile("cp.async.wait_group 0;\n");
    __syncthreads();

    // ---- pooling from smem: 9 warps, one 32x32 cell each ----
    {
        int w = t >> 5, lane = t & 31;
        int cy = w / 3, cx = w % 3;
        const float* cb = &tile[(cy * 32 + 1) * PITCH + cx * 32];
        float s = 0.f;
#pragma unroll
        for (int i = 0; i < 8; i++) {
            int f = lane + i * 32;
            int row = f >> 3, c4 = f & 7;
            float4 v = *reinterpret_cast<const float4*>(cb + row * PITCH + c4 * 4);
            s += v.x + v.y + v.z + v.w;
        }
#pragma unroll
        for (int o = 16; o; o >>= 1) s += __shfl_xor_sync(0xffffffffu, s, o);
        if (lane == 0) g_pooled[(b * 9 + w) * CC + c] = s;
    }
    __threadfence();
    __syncthreads();
    if (t == 0) s_ret = atomicAdd(&g_cnt[b], 1u);
    __syncthreads();
    unsigned ret = s_ret;
    unsigned R = ret >> 8;                 // run (replay) epoch
    bool isproj = ((ret & 255u) == 255u);  // 256th contributor for sample b

    if (isproj) {
        // ---- proj for whole sample b ----
        if (t == 0) { while (atomicAdd(&g_prep, 0u) < 114u * (R + 1u)) __nanosleep(64); }
        __syncthreads();
        __threadfence();

        if (t < CC) {
            float ss = 0.f;
#pragma unroll
            for (int p = 0; p < 9; p++) ss += g_pooled[(b * 9 + p) * CC + t];
            sgap[t] = ss;
        }
        __syncthreads();

        // GEMM1 + BN + exact GELU: 640 outputs
#pragma unroll
        for (int i = 0; i < 3; i++) {
            int item = t + i * 288;
            if (item < 640) {
                int p = item >> 6, o = item & 63;
                float acc = 0.f;
                if (p < 9) {
                    const float* P = &g_pooled[(b * 9 + p) * CC];
#pragma unroll 8
                    for (int k = 0; k < CC; k++) acc = fmaf(g_w1t[k * CR + o], P[k], acc);
                    acc *= (1.0f / 1024.0f);
                } else {
#pragma unroll 8
                    for (int k = 0; k < CC; k++) acc = fmaf(g_w1t[k * CR + o], sgap[k], acc);
                    acc *= (1.0f / 9216.0f);
                }
                float h = acc + g_bnb[o];
                h = 0.5f * h * (1.0f + erff(h * 0.70710678118654752f));
                sh[item] = h;
            }
        }
        __syncthreads();

        // GEMM2 + softmax + mix, one thread per channel
        if (t < CC) {
            float a0[10], a1[10];
            float b0v = b2[t], b1v = b2[CC + t];
#pragma unroll
            for (int p = 0; p < 10; p++) { a0[p] = b0v; a1[p] = b1v; }
            for (int k = 0; k < CR; k++) {
                float w_0 = g_w2t[k * 512 + t];
                float w_1 = g_w2t[k * 512 + CC + t];
#pragma unroll
                for (int p = 0; p < 10; p++) {
                    float hv = sh[p * 64 + k];
                    a0[p] = fmaf(w_0, hv, a0[p]);
                    a1[p] = fmaf(w_1, hv, a1[p]);
                }
            }
#pragma unroll
            for (int p = 0; p < 10; p++) {
                float m = fmaxf(a0[p], a1[p]);
                float e0 = __expf(a0[p] - m), e1 = __expf(a1[p] - m);
                float r = 1.0f / (e0 + e1);
                float p0 = e0 * r, p1 = e1 * r;
                if (p < 9)
                    g_weight[(b * 9 + p) * CC + t] = p0 * g_dwt[p * CC + t]
                                                   + p1 * g_dwt[(9 + p) * CC + t];
                else
                    g_bias[b * CC + t] = p0 * dyn_bias[t] + p1 * dyn_bias[CC + t];
            }
        }
        __threadfence();
        __syncthreads();
        if (t == 0) atomicAdd(&g_done[b], 1u);
    } else {
        // wait for sample b's weights
        if (t == 0) { while (atomicAdd(&g_done[b], 0u) < R + 1u) __nanosleep(128); }
        __syncthreads();
        __threadfence();
    }

    // ---- depthwise conv from the resident tile ----
    float w0 = g_weight[(b*9+0)*CC+c], w1_ = g_weight[(b*9+1)*CC+c], w2_ = g_weight[(b*9+2)*CC+c];
    float w3 = g_weight[(b*9+3)*CC+c], w4  = g_weight[(b*9+4)*CC+c], w5  = g_weight[(b*9+5)*CC+c];
    float w6 = g_weight[(b*9+6)*CC+c], w7  = g_weight[(b*9+7)*CC+c], w8  = g_weight[(b*9+8)*CC+c];
    float bv = g_bias[bc];

    int tx = t % 24;
    int ty = t / 24;
    int x0 = tx * 4;
    int r0 = ty * 8;
    bool hasL = (tx > 0), hasR = (tx < 23);

    float4 aA = make_float4(0.f,0.f,0.f,0.f);
    float4 aB = make_float4(0.f,0.f,0.f,0.f);
    float4 aC = make_float4(0.f,0.f,0.f,0.f);

#pragma unroll
    for (int s = 0; s < 10; ++s) {
        const float* row = &tile[(r0 + s) * PITCH + x0];
        float4 v = *reinterpret_cast<const float4*>(row);
        float l  = hasL ? row[-1] : 0.f;
        float rr = hasR ? row[4]  : 0.f;
        float c0 = v.x, c1 = v.y, c2 = v.z, c3 = v.w;

        aA.x = fmaf(l,  w6, fmaf(c0, w7, fmaf(c1, w8, aA.x)));
        aA.y = fmaf(c0, w6, fmaf(c1, w7, fmaf(c2, w8, aA.y)));
        aA.z = fmaf(c1, w6, fmaf(c2, w7, fmaf(c3, w8, aA.z)));
        aA.w = fmaf(c2, w6, fmaf(c3, w7, fmaf(rr, w8, aA.w)));

        aB.x = fmaf(l,  w3, fmaf(c0, w4, fmaf(c1, w5, aB.x)));
        aB.y = fmaf(c0, w3, fmaf(c1, w4, fmaf(c2, w5, aB.y)));
        aB.z = fmaf(c1, w3, fmaf(c2, w4, fmaf(c3, w5, aB.z)));
        aB.w = fmaf(c2, w3, fmaf(c3, w4, fmaf(rr, w5, aB.w)));

        aC.x = fmaf(l,  w0, fmaf(c0, w1_, fmaf(c1, w2_, aC.x)));
        aC.y = fmaf(c0, w0, fmaf(c1, w1_, fmaf(c2, w2_, aC.y)));
        aC.z = fmaf(c1, w0, fmaf(c2, w1_, fmaf(c3, w2_, aC.z)));
        aC.w = fmaf(c2, w0, fmaf(c3, w1_, fmaf(rr, w2_, aC.w)));

        if (s >= 2) {
            int yo = r0 + s - 2;
            float4 o;
            o.x = aA.x + bv; o.y = aA.y + bv; o.z = aA.z + bv; o.w = aA.w + bv;
            __stcs(reinterpret_cast<float4*>(outimg + yo * WW + x0), o);
        }
        aA = aB; aB = aC;
        aC = make_float4(0.f,0.f,0.f,0.f);
    }
}

extern "C" void kernel_launch(void* const* d_in, const int* in_sizes, int n_in,
                              void* d_out, int out_size) {
    const float* x          = (const float*)d_in[0];
    const float* dyn_weight = (const float*)d_in[1];
    const float* dyn_bias   = (const float*)d_in[2];
    const float* w1         = (const float*)d_in[3];
    const float* bn_gamma   = (const float*)d_in[4];
    const float* bn_beta    = (const float*)d_in[5];
    const float* bn_mean    = (const float*)d_in[6];
    const float* bn_var     = (const float*)d_in[7];
    const float* w2         = (const float*)d_in[8];
    const float* b2         = (const float*)d_in[9];
    float* out = (float*)d_out;

    fused_kernel<<<BB*CC, 288>>>(x, dyn_weight, dyn_bias, w1, bn_gamma, bn_beta,
                                 bn_mean, bn_var, w2, b2, out);
}

// round 10
// speedup vs baseline: 3.0830x; 3.0830x over previous
#include <cuda_runtime.h>
#include <math.h>

#define BB 32
#define CC 256
#define HH 96
#define WW 96
#define CR 64
#define PITCH 96
#define CHK 4                 // samples per chunk
#define NCH (BB/CHK)          // 8 chunks
#define POOLB (CHK*CC)        // 1024
#define PROJB (5*CHK)         // 20

// Scratch (no allocs allowed)
__device__ float g_pooled[BB*9*CC];     // [b][p][c] block sums
__device__ float g_weight[BB*9*CC];     // [b][p][c]
__device__ float g_bias[BB*CC];
__device__ float g_w1t[CC*CR];          // [k][o], BN inv folded
__device__ float g_w2t[CR*2*CC];        // [k][n]
__device__ float g_bnb[CR];
__device__ float g_dwt[2*9*CC];         // [g][p][c]
__device__ unsigned g_cnv[BB];          // conv arrivals (256/sample/run, never reset)
__device__ unsigned g_done[BB];         // proj completions (5/sample/run, never reset)

// ---------------------------------------------------------------------------
// pool work for one (b,c): 9 warps, one 32x32 cell each. PLAIN loads so the
// chunk stays resident in L2 for the following conv launch.
// ---------------------------------------------------------------------------
__device__ __forceinline__ void pool_work(const float* __restrict__ x, int bc, int t) {
    int w = t >> 5, lane = t & 31;
    int cy = w / 3, cx = w % 3;
    const float* base = x + (size_t)bc * (HH*WW) + cy * 32 * WW + cx * 32;
    float s = 0.f;
#pragma unroll
    for (int i = 0; i < 8; i++) {
        int f = lane + i * 32;
        int row = f >> 3, c4 = f & 7;
        float4 v = *reinterpret_cast<const float4*>(base + row * WW + c4 * 4);
        s += v.x + v.y + v.z + v.w;
    }
#pragma unroll
    for (int o = 16; o; o >>= 1) s += __shfl_xor_sync(0xffffffffu, s, o);
    if (lane == 0)
        g_pooled[((bc >> 8) * 9 + w) * CC + (bc & 255)] = s;
}

// ---------------------------------------------------------------------------
// Kernel A: pool chunk 0 + prep (blocks 0..113, hidden under DRAM time).
// ---------------------------------------------------------------------------
__global__ __launch_bounds__(288) void pool0_kernel(
    const float* __restrict__ x,
    const float* __restrict__ w1,
    const float* __restrict__ bn_gamma,
    const float* __restrict__ bn_beta,
    const float* __restrict__ bn_mean,
    const float* __restrict__ bn_var,
    const float* __restrict__ w2,
    const float* __restrict__ dyn_weight)
{
    int bc = blockIdx.x;                  // 0..1023 -> chunk 0
    int t = threadIdx.x;
    if (bc < 114) {
        int idx = bc * 288 + t;
        if (idx < CC*CR) {
            int k = idx >> 6, o = idx & 63;
            float inv = bn_gamma[o] * rsqrtf(bn_var[o] + 1e-5f);
            g_w1t[idx] = w1[o * CC + k] * inv;
        }
        if (idx < CR*2*CC) {
            int k = idx >> 9, n = idx & 511;
            g_w2t[idx] = w2[n * CR + k];
        }
        if (idx < 2*9*CC) {
            int g = idx / (9*CC);
            int rem = idx - g * 9 * CC;
            int p = rem >> 8, c2 = rem & 255;
            g_dwt[idx] = dyn_weight[(g * CC + c2) * 9 + p];
        }
        if (idx < CR) {
            float inv = bn_gamma[idx] * rsqrtf(bn_var[idx] + 1e-5f);
            g_bnb[idx] = bn_beta[idx] - bn_mean[idx] * inv;
        }
    }
    pool_work(x, bc, t);
}

// ---------------------------------------------------------------------------
// proj work: block handles positions pq and pq+5 for one sample (projf body).
// 256 active threads of 288. Increments g_done[b] when finished.
// ---------------------------------------------------------------------------
__device__ __forceinline__ void proj_work(int b, int pq, int t,
                                          const float* __restrict__ dyn_bias,
                                          const float* __restrict__ b2,
                                          float* sv0, float* sv1, float* pa,
                                          float* sh0, float* sh1)
{
    int p = pq, p2 = pq + 5;
    if (t < CC) {
        float v0 = g_pooled[(b * 9 + p) * CC + t] * (1.0f / 1024.0f);
        float v1;
        if (p2 < 9) {
            v1 = g_pooled[(b * 9 + p2) * CC + t] * (1.0f / 1024.0f);
        } else {
            float s = 0.f;
#pragma unroll
            for (int q = 0; q < 9; q++) s += g_pooled[(b * 9 + q) * CC + t];
            v1 = s * (1.0f / (HH * WW));
        }
        sv0[t] = v0; sv1[t] = v1;
    }
    __syncthreads();

    if (t < 256) {
        int o = t & 63, slice = t >> 6;
        const float* w1s = g_w1t + slice * 64 * CR + o;
        const float* a0p = sv0 + slice * 64;
        const float* a1p = sv1 + slice * 64;
        float acc0 = 0.f, acc1 = 0.f;
#pragma unroll 8
        for (int k = 0; k < 64; k++) {
            float w = w1s[k * CR];
            acc0 = fmaf(w, a0p[k], acc0);
            acc1 = fmaf(w, a1p[k], acc1);
        }
        pa[t] = acc0; pa[256 + t] = acc1;
    }
    __syncthreads();

    if (t < 128) {
        int pos = t >> 6, oo = t & 63;
        const float* pp = pa + pos * 256;
        float h = pp[oo] + pp[oo + 64] + pp[oo + 128] + pp[oo + 192] + g_bnb[oo];
        h = 0.5f * h * (1.0f + erff(h * 0.70710678118654752f));
        if (pos) sh1[oo] = h; else sh0[oo] = h;
    }
    __syncthreads();

    if (t < CC) {
        int c = t;
        float a0 = b2[c], a1 = b2[CC + c];
        float d0 = a0, d1 = a1;
#pragma unroll 8
        for (int k = 0; k < CR; k++) {
            float w_0 = g_w2t[k * 512 + c];
            float w_1 = g_w2t[k * 512 + CC + c];
            float h0 = sh0[k], h1 = sh1[k];
            a0 = fmaf(w_0, h0, a0); a1 = fmaf(w_1, h0, a1);
            d0 = fmaf(w_0, h1, d0); d1 = fmaf(w_1, h1, d1);
        }
        {
            float m = fmaxf(a0, a1);
            float e0 = __expf(a0 - m), e1 = __expf(a1 - m);
            float r = 1.0f / (e0 + e1);
            g_weight[(b * 9 + p) * CC + c] = e0 * r * g_dwt[p * CC + c]
                                           + e1 * r * g_dwt[(9 + p) * CC + c];
        }
        {
            float m = fmaxf(d0, d1);
            float e0 = __expf(d0 - m), e1 = __expf(d1 - m);
            float r = 1.0f / (e0 + e1);
            if (p2 < 9) {
                g_weight[(b * 9 + p2) * CC + c] = e0 * r * g_dwt[p2 * CC + c]
                                                + e1 * r * g_dwt[(9 + p2) * CC + c];
            } else {
                g_bias[b * CC + c] = e0 * r * dyn_bias[c] + e1 * r * dyn_bias[CC + c];
            }
        }
    }
    __threadfence();
    __syncthreads();
    if (t == 0) atomicAdd(&g_done[b], 1u);
}

// ---------------------------------------------------------------------------
// conv work for one (b,c): stage from L2 via cp.async, spin (briefly) on this
// sample's 5 proj blocks (same launch, bids 0..19, scheduled first), conv.
// ---------------------------------------------------------------------------
__device__ __forceinline__ void conv_work(const float* __restrict__ x,
                                          float* __restrict__ y,
                                          int bc, int t,
                                          float* tile, unsigned* s_u)
{
    const float* img = x + (size_t)bc * (HH*WW);
    float* outimg = y + (size_t)bc * (HH*WW);
    int b = bc >> 8, c = bc & 255;

    float4 z4 = make_float4(0.f,0.f,0.f,0.f);
    if (t < 24) {
        *reinterpret_cast<float4*>(&tile[t * 4]) = z4;
    } else if (t < 48) {
        *reinterpret_cast<float4*>(&tile[97 * PITCH + (t - 24) * 4]) = z4;
    }

#pragma unroll
    for (int i = 0; i < 8; i++) {
        int idx = t + i * 288;
        int r = idx / 24, j = idx % 24;
        unsigned sa = (unsigned)__cvta_generic_to_shared(&tile[(r + 1) * PITCH + j * 4]);
        asm volatile("cp.async.cg.shared.global [%0], [%1], 16;\n"
                     :: "r"(sa), "l"(img + r * WW + j * 4));
    }
    asm volatile("cp.async.commit_group;\n");

    // epoch-safe wait for this sample's proj (5 blocks/run)
    if (t == 0) {
        unsigned ret = atomicAdd(&g_cnv[b], 1u);
        unsigned R = ret >> 8;
        while (atomicAdd(&g_done[b], 0u) < 5u * (R + 1u)) __nanosleep(64);
        *s_u = 1u;
    }
    __syncthreads();
    __threadfence();

    float w0 = g_weight[(b*9+0)*CC+c], w1_ = g_weight[(b*9+1)*CC+c], w2_ = g_weight[(b*9+2)*CC+c];
    float w3 = g_weight[(b*9+3)*CC+c], w4  = g_weight[(b*9+4)*CC+c], w5  = g_weight[(b*9+5)*CC+c];
    float w6 = g_weight[(b*9+6)*CC+c], w7  = g_weight[(b*9+7)*CC+c], w8  = g_weight[(b*9+8)*CC+c];
    float bv = g_bias[bc];

    asm volatile("cp.async.wait_group 0;\n");
    __syncthreads();

    int tx = t % 24;
    int ty = t / 24;
    int x0 = tx * 4;
    int r0 = ty * 8;
    bool hasL = (tx > 0), hasR = (tx < 23);

    float4 aA = make_float4(0.f,0.f,0.f,0.f);
    float4 aB = make_float4(0.f,0.f,0.f,0.f);
    float4 aC = make_float4(0.f,0.f,0.f,0.f);

#pragma unroll
    for (int s = 0; s < 10; ++s) {
        const float* row = &tile[(r0 + s) * PITCH + x0];
        float4 v = *reinterpret_cast<const float4*>(row);
        float l  = hasL ? row[-1] : 0.f;
        float rr = hasR ? row[4]  : 0.f;
        float c0 = v.x, c1 = v.y, c2 = v.z, c3 = v.w;

        aA.x = fmaf(l,  w6, fmaf(c0, w7, fmaf(c1, w8, aA.x)));
        aA.y = fmaf(c0, w6, fmaf(c1, w7, fmaf(c2, w8, aA.y)));
        aA.z = fmaf(c1, w6, fmaf(c2, w7, fmaf(c3, w8, aA.z)));
        aA.w = fmaf(c2, w6, fmaf(c3, w7, fmaf(rr, w8, aA.w)));

        aB.x = fmaf(l,  w3, fmaf(c0, w4, fmaf(c1, w5, aB.x)));
        aB.y = fmaf(c0, w3, fmaf(c1, w4, fmaf(c2, w5, aB.y)));
        aB.z = fmaf(c1, w3, fmaf(c2, w4, fmaf(c3, w5, aB.z)));
        aB.w = fmaf(c2, w3, fmaf(c3, w4, fmaf(rr, w5, aB.w)));

        aC.x = fmaf(l,  w0, fmaf(c0, w1_, fmaf(c1, w2_, aC.x)));
        aC.y = fmaf(c0, w0, fmaf(c1, w1_, fmaf(c2, w2_, aC.y)));
        aC.z = fmaf(c1, w0, fmaf(c2, w1_, fmaf(c3, w2_, aC.z)));
        aC.w = fmaf(c2, w0, fmaf(c3, w1_, fmaf(rr, w2_, aC.w)));

        if (s >= 2) {
            int yo = r0 + s - 2;
            float4 o;
            o.x = aA.x + bv; o.y = aA.y + bv; o.z = aA.z + bv; o.w = aA.w + bv;
            __stcs(reinterpret_cast<float4*>(outimg + yo * WW + x0), o);
        }
        aA = aB; aB = aC;
        aC = make_float4(0.f,0.f,0.f,0.f);
    }
}

// ---------------------------------------------------------------------------
// Kernel B: combo. bid 0..19: proj(conv_chunk); 20..1043: pool(pool_chunk);
// 1044..2067: conv(conv_chunk). Proj scheduled first (lowest bids).
// ---------------------------------------------------------------------------
__global__ __launch_bounds__(288, 5) void combo_kernel(
    const float* __restrict__ x, float* __restrict__ y,
    const float* __restrict__ dyn_bias, const float* __restrict__ b2,
    int pool_chunk)
{
    __shared__ float tile[98 * PITCH];
    __shared__ float sv0[CC], sv1[CC], pa[2*256], sh0[CR], sh1[CR];
    __shared__ unsigned s_u;
    int bid = blockIdx.x, t = threadIdx.x;
    int conv_chunk = pool_chunk - 1;

    if (bid < PROJB) {
        int pq = bid % 5, bsub = bid / 5;
        proj_work(conv_chunk * CHK + bsub, pq, t, dyn_bias, b2, sv0, sv1, pa, sh0, sh1);
    } else if (bid < PROJB + POOLB) {
        pool_work(x, pool_chunk * POOLB + (bid - PROJB), t);
    } else {
        conv_work(x, y, conv_chunk * POOLB + (bid - PROJB - POOLB), t, tile, &s_u);
    }
}

// ---------------------------------------------------------------------------
// Kernel C: final. bid 0..19: proj(last chunk); 20..1043: conv(last chunk).
// ---------------------------------------------------------------------------
__global__ __launch_bounds__(288, 5) void final_kernel(
    const float* __restrict__ x, float* __restrict__ y,
    const float* __restrict__ dyn_bias, const float* __restrict__ b2)
{
    __shared__ float tile[98 * PITCH];
    __shared__ float sv0[CC], sv1[CC], pa[2*256], sh0[CR], sh1[CR];
    __shared__ unsigned s_u;
    int bid = blockIdx.x, t = threadIdx.x;
    int chunk = NCH - 1;

    if (bid < PROJB) {
        int pq = bid % 5, bsub = bid / 5;
        proj_work(chunk * CHK + bsub, pq, t, dyn_bias, b2, sv0, sv1, pa, sh0, sh1);
    } else {
        conv_work(x, y, chunk * POOLB + (bid - PROJB), t, tile, &s_u);
    }
}

extern "C" void kernel_launch(void* const* d_in, const int* in_sizes, int n_in,
                              void* d_out, int out_size) {
    const float* x          = (const float*)d_in[0];
    const float* dyn_weight = (const float*)d_in[1];
    const float* dyn_bias   = (const float*)d_in[2];
    const float* w1         = (const float*)d_in[3];
    const float* bn_gamma   = (const float*)d_in[4];
    const float* bn_beta    = (const float*)d_in[5];
    const float* bn_mean    = (const float*)d_in[6];
    const float* bn_var     = (const float*)d_in[7];
    const float* w2         = (const float*)d_in[8];
    const float* b2         = (const float*)d_in[9];
    float* out = (float*)d_out;

    pool0_kernel<<<POOLB, 288>>>(x, w1, bn_gamma, bn_beta, bn_mean, bn_var, w2, dyn_weight);
    for (int i = 1; i < NCH; i++)
        combo_kernel<<<PROJB + 2*POOLB, 288>>>(x, out, dyn_bias, b2, i);
    final_kernel<<<PROJB + POOLB, 288>>>(x, out, dyn_bias, b2);
}

// round 11
// speedup vs baseline: 4.5744x; 1.4838x over previous
#include <cuda_runtime.h>
#include <math.h>

#define BB 32
#define CC 256
#define HH 96
#define WW 96
#define CR 64
#define PITCH 96

// Scratch (no allocs allowed)
__device__ float g_pooled[BB*9*CC];     // [b][p][c] block sums
__device__ float g_weight[BB*9*CC];     // [b][p][c]
__device__ float g_bias[BB*CC];
__device__ float g_w1t[CC*CR];          // [k][o], BN inv folded
__device__ float g_w2t[CR*2*CC];        // [k][n]
__device__ float g_bnb[CR];
__device__ float g_dwt[2*9*CC];         // [g][p][c]
__device__ unsigned g_cnt[BB];          // pool contributions (256/sample/run, never reset)
__device__ unsigned g_prep;             // prep contributions (114/run, never reset)

// ---------------------------------------------------------------------------
// Kernel 1: pooling + prep + (last-block-per-sample) FULL proj.
// 8192 blocks x 288 threads. Blocks 0..113 also do prep (transposes+BN fold).
// The 256th finisher per sample computes weights/bias for all 256 channels,
// coalesced, overlapped with the rest of the grid's streaming.
// ---------------------------------------------------------------------------
__global__ void pool_kernel(const float* __restrict__ x,
                            const float* __restrict__ dyn_weight,
                            const float* __restrict__ dyn_bias,
                            const float* __restrict__ w1,
                            const float* __restrict__ bn_gamma,
                            const float* __restrict__ bn_beta,
                            const float* __restrict__ bn_mean,
                            const float* __restrict__ bn_var,
                            const float* __restrict__ w2,
                            const float* __restrict__ b2) {
    __shared__ float sh[640];
    __shared__ float sgap[CC];
    __shared__ unsigned s_ret;
    int bc = blockIdx.x;
    int t = threadIdx.x;
    int b = bc >> 8, c = bc & 255;

    // prep: 114*288 = 32832 >= 32768 items, hidden under pool DRAM time
    if (bc < 114) {
        int idx = bc * 288 + t;
        if (idx < CC*CR) {
            int k = idx >> 6, o = idx & 63;
            float inv = bn_gamma[o] * rsqrtf(bn_var[o] + 1e-5f);
            g_w1t[idx] = w1[o * CC + k] * inv;
        }
        if (idx < CR*2*CC) {
            int k = idx >> 9, n = idx & 511;
            g_w2t[idx] = w2[n * CR + k];
        }
        if (idx < 2*9*CC) {
            int g = idx / (9*CC);
            int rem = idx - g * 9 * CC;
            int p = rem >> 8, c2 = rem & 255;
            g_dwt[idx] = dyn_weight[(g * CC + c2) * 9 + p];
        }
        if (idx < CR) {
            float inv = bn_gamma[idx] * rsqrtf(bn_var[idx] + 1e-5f);
            g_bnb[idx] = bn_beta[idx] - bn_mean[idx] * inv;
        }
        __threadfence();
        __syncthreads();
        if (t == 0) atomicAdd(&g_prep, 1u);
    }

    // pooling: 9 warps, one 32x32 cell each
    {
        int w = t >> 5, lane = t & 31;
        int cy = w / 3, cx = w % 3;
        const float* base = x + (size_t)bc * (HH*WW) + cy * 32 * WW + cx * 32;
        float s = 0.f;
#pragma unroll
        for (int i = 0; i < 8; i++) {
            int f = lane + i * 32;
            int row = f >> 3, c4 = f & 7;
            float4 v = __ldcs(reinterpret_cast<const float4*>(base + row * WW + c4 * 4));
            s += v.x + v.y + v.z + v.w;
        }
#pragma unroll
        for (int o = 16; o; o >>= 1) s += __shfl_xor_sync(0xffffffffu, s, o);
        if (lane == 0) g_pooled[(b * 9 + w) * CC + c] = s;
    }
    __threadfence();
    __syncthreads();
    if (t == 0) s_ret = atomicAdd(&g_cnt[b], 1u);
    __syncthreads();
    unsigned ret = s_ret;
    unsigned R = ret >> 8;                 // run (replay) epoch
    if ((ret & 255u) != 255u) return;      // not the last finisher for sample b

    // ---- FULL proj for sample b ----
    if (t == 0) { while (atomicAdd(&g_prep, 0u) < 114u * (R + 1u)) __nanosleep(64); }
    __syncthreads();
    __threadfence();

    if (t < CC) {
        float ss = 0.f;
#pragma unroll
        for (int p = 0; p < 9; p++) ss += g_pooled[(b * 9 + p) * CC + t];
        sgap[t] = ss;
    }
    __syncthreads();

    // GEMM1 + BN + exact GELU: 640 outputs (10 pos x 64)
#pragma unroll
    for (int i = 0; i < 3; i++) {
        int item = t + i * 288;
        if (item < 640) {
            int p = item >> 6, o = item & 63;
            float acc = 0.f;
            if (p < 9) {
                const float* P = &g_pooled[(b * 9 + p) * CC];
#pragma unroll 8
                for (int k = 0; k < CC; k++) acc = fmaf(g_w1t[k * CR + o], P[k], acc);
                acc *= (1.0f / 1024.0f);
            } else {
#pragma unroll 8
                for (int k = 0; k < CC; k++) acc = fmaf(g_w1t[k * CR + o], sgap[k], acc);
                acc *= (1.0f / 9216.0f);
            }
            float h = acc + g_bnb[o];
            h = 0.5f * h * (1.0f + erff(h * 0.70710678118654752f));
            sh[item] = h;
        }
    }
    __syncthreads();

    // GEMM2 + softmax + mix: one thread per channel, coalesced w2t reads
    if (t < CC) {
        float a0[10], a1[10];
        float b0v = b2[t], b1v = b2[CC + t];
#pragma unroll
        for (int p = 0; p < 10; p++) { a0[p] = b0v; a1[p] = b1v; }
        for (int k = 0; k < CR; k++) {
            float w_0 = g_w2t[k * 512 + t];
            float w_1 = g_w2t[k * 512 + CC + t];
#pragma unroll
            for (int p = 0; p < 10; p++) {
                float hv = sh[p * 64 + k];
                a0[p] = fmaf(w_0, hv, a0[p]);
                a1[p] = fmaf(w_1, hv, a1[p]);
            }
        }
#pragma unroll
        for (int p = 0; p < 10; p++) {
            float m = fmaxf(a0[p], a1[p]);
            float e0 = __expf(a0[p] - m), e1 = __expf(a1[p] - m);
            float r = 1.0f / (e0 + e1);
            float p0 = e0 * r, p1 = e1 * r;
            if (p < 9)
                g_weight[(b * 9 + p) * CC + t] = p0 * g_dwt[p * CC + t]
                                               + p1 * g_dwt[(9 + p) * CC + t];
            else
                g_bias[b * CC + t] = p0 * dyn_bias[t] + p1 * dyn_bias[CC + t];
        }
    }
}

// ---------------------------------------------------------------------------
// Kernel 2: depthwise 3x3 conv + bias. PITCH=96, predicated column edges,
// cp.async staging, 6 blocks/SM. (R8 version, unchanged.)
// ---------------------------------------------------------------------------
__global__ __launch_bounds__(288, 6) void dwconv_kernel(const float* __restrict__ x,
                                                        float* __restrict__ y) {
    __shared__ float tile[98 * PITCH];
    int bc = blockIdx.x;
    int t = threadIdx.x;
    const float* img = x + (size_t)bc * (HH*WW);
    float* outimg = y + (size_t)bc * (HH*WW);

    float4 z4 = make_float4(0.f,0.f,0.f,0.f);
    if (t < 24) {
        *reinterpret_cast<float4*>(&tile[t * 4]) = z4;
    } else if (t < 48) {
        *reinterpret_cast<float4*>(&tile[97 * PITCH + (t - 24) * 4]) = z4;
    }

#pragma unroll
    for (int i = 0; i < 8; i++) {
        int idx = t + i * 288;
        int r = idx / 24, j = idx % 24;
        unsigned sa = (unsigned)__cvta_generic_to_shared(&tile[(r + 1) * PITCH + j * 4]);
        asm volatile("cp.async.cg.shared.global [%0], [%1], 16;\n"
                     :: "r"(sa), "l"(img + r * WW + j * 4));
    }
    asm volatile("cp.async.commit_group;\n");
    asm volatile("cp.async.wait_group 0;\n");
    __syncthreads();

    int b = bc >> 8, c = bc & 255;
    float w0 = g_weight[(b*9+0)*CC+c], w1_ = g_weight[(b*9+1)*CC+c], w2_ = g_weight[(b*9+2)*CC+c];
    float w3 = g_weight[(b*9+3)*CC+c], w4  = g_weight[(b*9+4)*CC+c], w5  = g_weight[(b*9+5)*CC+c];
    float w6 = g_weight[(b*9+6)*CC+c], w7  = g_weight[(b*9+7)*CC+c], w8  = g_weight[(b*9+8)*CC+c];
    float bv = g_bias[bc];

    int tx = t % 24;
    int ty = t / 24;
    int x0 = tx * 4;
    int r0 = ty * 8;
    bool hasL = (tx > 0), hasR = (tx < 23);

    float4 aA = make_float4(0.f,0.f,0.f,0.f);
    float4 aB = make_float4(0.f,0.f,0.f,0.f);
    float4 aC = make_float4(0.f,0.f,0.f,0.f);

#pragma unroll
    for (int s = 0; s < 10; ++s) {
        const float* row = &tile[(r0 + s) * PITCH + x0];
        float4 v = *reinterpret_cast<const float4*>(row);
        float l  = hasL ? row[-1] : 0.f;
        float rr = hasR ? row[4]  : 0.f;
        float c0 = v.x, c1 = v.y, c2 = v.z, c3 = v.w;

        aA.x = fmaf(l,  w6, fmaf(c0, w7, fmaf(c1, w8, aA.x)));
        aA.y = fmaf(c0, w6, fmaf(c1, w7, fmaf(c2, w8, aA.y)));
        aA.z = fmaf(c1, w6, fmaf(c2, w7, fmaf(c3, w8, aA.z)));
        aA.w = fmaf(c2, w6, fmaf(c3, w7, fmaf(rr, w8, aA.w)));

        aB.x = fmaf(l,  w3, fmaf(c0, w4, fmaf(c1, w5, aB.x)));
        aB.y = fmaf(c0, w3, fmaf(c1, w4, fmaf(c2, w5, aB.y)));
        aB.z = fmaf(c1, w3, fmaf(c2, w4, fmaf(c3, w5, aB.z)));
        aB.w = fmaf(c2, w3, fmaf(c3, w4, fmaf(rr, w5, aB.w)));

        aC.x = fmaf(l,  w0, fmaf(c0, w1_, fmaf(c1, w2_, aC.x)));
        aC.y = fmaf(c0, w0, fmaf(c1, w1_, fmaf(c2, w2_, aC.y)));
        aC.z = fmaf(c1, w0, fmaf(c2, w1_, fmaf(c3, w2_, aC.z)));
        aC.w = fmaf(c2, w0, fmaf(c3, w1_, fmaf(rr, w2_, aC.w)));

        if (s >= 2) {
            int yo = r0 + s - 2;
            float4 o;
            o.x = aA.x + bv; o.y = aA.y + bv; o.z = aA.z + bv; o.w = aA.w + bv;
            __stcs(reinterpret_cast<float4*>(outimg + yo * WW + x0), o);
        }
        aA = aB; aB = aC;
        aC = make_float4(0.f,0.f,0.f,0.f);
    }
}

extern "C" void kernel_launch(void* const* d_in, const int* in_sizes, int n_in,
                              void* d_out, int out_size) {
    const float* x          = (const float*)d_in[0];
    const float* dyn_weight = (const float*)d_in[1];
    const float* dyn_bias   = (const float*)d_in[2];
    const float* w1         = (const float*)d_in[3];
    const float* bn_gamma   = (const float*)d_in[4];
    const float* bn_beta    = (const float*)d_in[5];
    const float* bn_mean    = (const float*)d_in[6];
    const float* bn_var     = (const float*)d_in[7];
    const float* w2         = (const float*)d_in[8];
    const float* b2         = (const float*)d_in[9];
    float* out = (float*)d_out;

    pool_kernel<<<BB*CC, 288>>>(x, dyn_weight, dyn_bias, w1, bn_gamma, bn_beta,
                                bn_mean, bn_var, w2, b2);
    dwconv_kernel<<<BB*CC, 288>>>(x, out);
}

// round 12
// speedup vs baseline: 5.0474x; 1.1034x over previous
#include <cuda_runtime.h>
#include <math.h>

#define BB 32
#define CC 256
#define HH 96
#define WW 96
#define CR 64
#define PITCH 96
#define PROJB (5*BB)          // 160 proj blocks (5 per sample)

// Scratch (no allocs allowed)
__device__ float g_pooled[BB*9*CC];     // [b][p][c] block sums
__device__ float g_weight[BB*9*CC];     // [b][p][c]
__device__ float g_bias[BB*CC];
__device__ float g_w1t[CC*CR];          // [k][o], BN inv folded
__device__ float g_w2t[CR*2*CC];        // [k][n]
__device__ float g_bnb[CR];
__device__ float g_dwt[2*9*CC];         // [g][p][c]
__device__ unsigned g_cnv[BB];          // conv arrivals (256/sample/run, never reset)
__device__ unsigned g_done[BB];         // proj completions (5/sample/run, never reset)

// ---------------------------------------------------------------------------
// Kernel 1: per-(b,c) 3x3 block sums + prep (blocks 0..113). R8 version.
// ---------------------------------------------------------------------------
__global__ void pool_kernel(const float* __restrict__ x,
                            const float* __restrict__ w1,
                            const float* __restrict__ bn_gamma,
                            const float* __restrict__ bn_beta,
                            const float* __restrict__ bn_mean,
                            const float* __restrict__ bn_var,
                            const float* __restrict__ w2,
                            const float* __restrict__ dyn_weight) {
    int bc = blockIdx.x;

    if (bc < 114) {
        int idx = bc * 288 + threadIdx.x;
        if (idx < CC*CR) {
            int k = idx >> 6, o = idx & 63;
            float inv = bn_gamma[o] * rsqrtf(bn_var[o] + 1e-5f);
            g_w1t[idx] = w1[o * CC + k] * inv;
        }
        if (idx < CR*2*CC) {
            int k = idx >> 9, n = idx & 511;
            g_w2t[idx] = w2[n * CR + k];
        }
        if (idx < 2*9*CC) {
            int g = idx / (9*CC);
            int rem = idx - g * 9 * CC;
            int p = rem >> 8, c = rem & 255;
            g_dwt[idx] = dyn_weight[(g * CC + c) * 9 + p];
        }
        if (idx < CR) {
            float inv = bn_gamma[idx] * rsqrtf(bn_var[idx] + 1e-5f);
            g_bnb[idx] = bn_beta[idx] - bn_mean[idx] * inv;
        }
    }

    int w = threadIdx.x >> 5;
    int lane = threadIdx.x & 31;
    int cy = w / 3, cx = w % 3;
    const float* base = x + (size_t)bc * (HH*WW) + cy * 32 * WW + cx * 32;
    float s = 0.f;
#pragma unroll
    for (int i = 0; i < 8; i++) {
        int f = lane + i * 32;
        int row = f >> 3, c4 = f & 7;
        float4 v = __ldcs(reinterpret_cast<const float4*>(base + row * WW + c4 * 4));
        s += v.x + v.y + v.z + v.w;
    }
#pragma unroll
    for (int o = 16; o; o >>= 1) s += __shfl_xor_sync(0xffffffffu, s, o);
    if (lane == 0)
        g_pooled[((bc >> 8) * 9 + w) * CC + (bc & 255)] = s;
}

// ---------------------------------------------------------------------------
// proj work (R10 version, proven): block handles positions pq and pq+5 for
// one sample. Scratch overlaid on the conv tile. Bumps g_done[b] at the end.
// ---------------------------------------------------------------------------
__device__ __forceinline__ void proj_work(int b, int pq, int t,
                                          const float* __restrict__ dyn_bias,
                                          const float* __restrict__ b2,
                                          float* scratch)
{
    float* sv0 = scratch;            // 256
    float* sv1 = scratch + 256;      // 256
    float* pa  = scratch + 512;      // 512
    float* sh0 = scratch + 1024;     // 64
    float* sh1 = scratch + 1088;     // 64
    int p = pq, p2 = pq + 5;

    if (t < CC) {
        float v0 = g_pooled[(b * 9 + p) * CC + t] * (1.0f / 1024.0f);
        float v1;
        if (p2 < 9) {
            v1 = g_pooled[(b * 9 + p2) * CC + t] * (1.0f / 1024.0f);
        } else {
            float s = 0.f;
#pragma unroll
            for (int q = 0; q < 9; q++) s += g_pooled[(b * 9 + q) * CC + t];
            v1 = s * (1.0f / (HH * WW));
        }
        sv0[t] = v0; sv1[t] = v1;
    }
    __syncthreads();

    if (t < 256) {
        int o = t & 63, slice = t >> 6;
        const float* w1s = g_w1t + slice * 64 * CR + o;
        const float* a0p = sv0 + slice * 64;
        const float* a1p = sv1 + slice * 64;
        float acc0 = 0.f, acc1 = 0.f;
#pragma unroll 8
        for (int k = 0; k < 64; k++) {
            float w = w1s[k * CR];
            acc0 = fmaf(w, a0p[k], acc0);
            acc1 = fmaf(w, a1p[k], acc1);
        }
        pa[t] = acc0; pa[256 + t] = acc1;
    }
    __syncthreads();

    if (t < 128) {
        int pos = t >> 6, oo = t & 63;
        const float* pp = pa + pos * 256;
        float h = pp[oo] + pp[oo + 64] + pp[oo + 128] + pp[oo + 192] + g_bnb[oo];
        h = 0.5f * h * (1.0f + erff(h * 0.70710678118654752f));
        if (pos) sh1[oo] = h; else sh0[oo] = h;
    }
    __syncthreads();

    if (t < CC) {
        int c = t;
        float a0 = b2[c], a1 = b2[CC + c];
        float d0 = a0, d1 = a1;
#pragma unroll 8
        for (int k = 0; k < CR; k++) {
            float w_0 = g_w2t[k * 512 + c];
            float w_1 = g_w2t[k * 512 + CC + c];
            float h0 = sh0[k], h1 = sh1[k];
            a0 = fmaf(w_0, h0, a0); a1 = fmaf(w_1, h0, a1);
            d0 = fmaf(w_0, h1, d0); d1 = fmaf(w_1, h1, d1);
        }
        {
            float m = fmaxf(a0, a1);
            float e0 = __expf(a0 - m), e1 = __expf(a1 - m);
            float r = 1.0f / (e0 + e1);
            g_weight[(b * 9 + p) * CC + c] = e0 * r * g_dwt[p * CC + c]
                                           + e1 * r * g_dwt[(9 + p) * CC + c];
        }
        {
            float m = fmaxf(d0, d1);
            float e0 = __expf(d0 - m), e1 = __expf(d1 - m);
            float r = 1.0f / (e0 + e1);
            if (p2 < 9) {
                g_weight[(b * 9 + p2) * CC + c] = e0 * r * g_dwt[p2 * CC + c]
                                                + e1 * r * g_dwt[(9 + p2) * CC + c];
            } else {
                g_bias[b * CC + c] = e0 * r * dyn_bias[c] + e1 * r * dyn_bias[CC + c];
            }
        }
    }
    __threadfence();
    __syncthreads();
    if (t == 0) atomicAdd(&g_done[b], 1u);
}

// ---------------------------------------------------------------------------
// Kernel 2: merged proj + depthwise conv.
// bids 0..159: proj (wave 1, depends only on previous launch).
// bids 160..8351: conv — stage via cp.async, epoch-wait on this sample's
// 5 proj blocks (overlapped with own DMA), then conv. 6 blocks/SM.
// ---------------------------------------------------------------------------
__global__ __launch_bounds__(288, 6) void dwconv_kernel(
    const float* __restrict__ x,
    const float* __restrict__ dyn_bias,
    const float* __restrict__ b2,
    float* __restrict__ y)
{
    __shared__ float tile[98 * PITCH];
    int bid = blockIdx.x;
    int t = threadIdx.x;

    if (bid < PROJB) {
        proj_work(bid / 5, bid % 5, t, dyn_bias, b2, tile);
        return;
    }

    int bc = bid - PROJB;
    int b = bc >> 8, c = bc & 255;
    const float* img = x + (size_t)bc * (HH*WW);
    float* outimg = y + (size_t)bc * (HH*WW);

    // zero halo rows 0 and 97
    float4 z4 = make_float4(0.f,0.f,0.f,0.f);
    if (t < 24) {
        *reinterpret_cast<float4*>(&tile[t * 4]) = z4;
    } else if (t < 48) {
        *reinterpret_cast<float4*>(&tile[97 * PITCH + (t - 24) * 4]) = z4;
    }

    // stage image: 2304 x 16B cp.async (DMA overlaps the proj wait below)
#pragma unroll
    for (int i = 0; i < 8; i++) {
        int idx = t + i * 288;
        int r = idx / 24, j = idx % 24;
        unsigned sa = (unsigned)__cvta_generic_to_shared(&tile[(r + 1) * PITCH + j * 4]);
        asm volatile("cp.async.cg.shared.global [%0], [%1], 16;\n"
                     :: "r"(sa), "l"(img + r * WW + j * 4));
    }
    asm volatile("cp.async.commit_group;\n");

    // epoch-safe wait for this sample's 5 proj blocks (same launch, wave 1)
    if (t == 0) {
        unsigned ret = atomicAdd(&g_cnv[b], 1u);
        unsigned R = ret >> 8;
        while (atomicAdd(&g_done[b], 0u) < 5u * (R + 1u)) __nanosleep(64);
    }
    __syncthreads();
    __threadfence();

    float w0 = g_weight[(b*9+0)*CC+c], w1_ = g_weight[(b*9+1)*CC+c], w2_ = g_weight[(b*9+2)*CC+c];
    float w3 = g_weight[(b*9+3)*CC+c], w4  = g_weight[(b*9+4)*CC+c], w5  = g_weight[(b*9+5)*CC+c];
    float w6 = g_weight[(b*9+6)*CC+c], w7  = g_weight[(b*9+7)*CC+c], w8  = g_weight[(b*9+8)*CC+c];
    float bv = g_bias[bc];

    asm volatile("cp.async.wait_group 0;\n");
    __syncthreads();

    int tx = t % 24;
    int ty = t / 24;
    int x0 = tx * 4;
    int r0 = ty * 8;
    bool hasL = (tx > 0), hasR = (tx < 23);

    float4 aA = make_float4(0.f,0.f,0.f,0.f);
    float4 aB = make_float4(0.f,0.f,0.f,0.f);
    float4 aC = make_float4(0.f,0.f,0.f,0.f);

#pragma unroll
    for (int s = 0; s < 10; ++s) {
        const float* row = &tile[(r0 + s) * PITCH + x0];
        float4 v = *reinterpret_cast<const float4*>(row);
        float l  = hasL ? row[-1] : 0.f;
        float rr = hasR ? row[4]  : 0.f;
        float c0 = v.x, c1 = v.y, c2 = v.z, c3 = v.w;

        aA.x = fmaf(l,  w6, fmaf(c0, w7, fmaf(c1, w8, aA.x)));
        aA.y = fmaf(c0, w6, fmaf(c1, w7, fmaf(c2, w8, aA.y)));
        aA.z = fmaf(c1, w6, fmaf(c2, w7, fmaf(c3, w8, aA.z)));
        aA.w = fmaf(c2, w6, fmaf(c3, w7, fmaf(rr, w8, aA.w)));

        aB.x = fmaf(l,  w3, fmaf(c0, w4, fmaf(c1, w5, aB.x)));
        aB.y = fmaf(c0, w3, fmaf(c1, w4, fmaf(c2, w5, aB.y)));
        aB.z = fmaf(c1, w3, fmaf(c2, w4, fmaf(c3, w5, aB.z)));
        aB.w = fmaf(c2, w3, fmaf(c3, w4, fmaf(rr, w5, aB.w)));

        aC.x = fmaf(l,  w0, fmaf(c0, w1_, fmaf(c1, w2_, aC.x)));
        aC.y = fmaf(c0, w0, fmaf(c1, w1_, fmaf(c2, w2_, aC.y)));
        aC.z = fmaf(c1, w0, fmaf(c2, w1_, fmaf(c3, w2_, aC.z)));
        aC.w = fmaf(c2, w0, fmaf(c3, w1_, fmaf(rr, w2_, aC.w)));

        if (s >= 2) {
            int yo = r0 + s - 2;
            float4 o;
            o.x = aA.x + bv; o.y = aA.y + bv; o.z = aA.z + bv; o.w = aA.w + bv;
            __stcs(reinterpret_cast<float4*>(outimg + yo * WW + x0), o);
        }
        aA = aB; aB = aC;
        aC = make_float4(0.f,0.f,0.f,0.f);
    }
}

extern "C" void kernel_launch(void* const* d_in, const int* in_sizes, int n_in,
                              void* d_out, int out_size) {
    const float* x          = (const float*)d_in[0];
    const float* dyn_weight = (const float*)d_in[1];
    const float* dyn_bias   = (const float*)d_in[2];
    const float* w1         = (const float*)d_in[3];
    const float* bn_gamma   = (const float*)d_in[4];
    const float* bn_beta    = (const float*)d_in[5];
    const float* bn_mean    = (const float*)d_in[6];
    const float* bn_var     = (const float*)d_in[7];
    const float* w2         = (const float*)d_in[8];
    const float* b2         = (const float*)d_in[9];
    float* out = (float*)d_out;

    pool_kernel<<<BB*CC, 288>>>(x, w1, bn_gamma, bn_beta, bn_mean, bn_var, w2, dyn_weight);
    dwconv_kernel<<<PROJB + BB*CC, 288>>>(x, dyn_bias, b2, out);
}

// round 13
// speedup vs baseline: 5.4123x; 1.0723x over previous
#include <cuda_runtime.h>
#include <math.h>

#define BB 32
#define CC 256
#define HH 96
#define WW 96
#define CR 64
#define PITCH 96
#define POOLN (BB*CC)         // 8192 pool blocks
#define PROJB (5*BB)          // 160 proj blocks

// Scratch (no allocs allowed)
__device__ float g_pooled[BB*9*CC];     // [b][p][c] block sums
__device__ float g_weight[BB*9*CC];     // [b][p][c]
__device__ float g_bias[BB*CC];
__device__ float g_w1t[CC*CR];          // [k][o], BN inv folded
__device__ float g_w2t[CR*2*CC];        // [k][n]
__device__ float g_bnb[CR];
__device__ float g_dwt[2*9*CC];         // [g][p][c]
__device__ unsigned g_cnt[BB];          // pool contributions (256/sample/launch, never reset)
__device__ unsigned g_prep;             // prep contributions (114/launch, never reset)
__device__ unsigned g_pepoch;           // proj arrivals (160/launch, never reset)

// ---------------------------------------------------------------------------
// Kernel 1: pool (bids 0..8191, wait-free) + proj (bids 8192..8351, spin on
// their sample's 256 pool contributions; scheduled last; <=160 of >=740
// slots can spin => pool always progresses => no deadlock).
// ---------------------------------------------------------------------------
__global__ __launch_bounds__(288, 7) void pool_proj_kernel(
    const float* __restrict__ x,
    const float* __restrict__ dyn_weight,
    const float* __restrict__ dyn_bias,
    const float* __restrict__ w1,
    const float* __restrict__ bn_gamma,
    const float* __restrict__ bn_beta,
    const float* __restrict__ bn_mean,
    const float* __restrict__ bn_var,
    const float* __restrict__ w2,
    const float* __restrict__ b2)
{
    __shared__ float scr[1216];   // proj scratch (sv0,sv1,pa,sh0,sh1)
    __shared__ unsigned s_u;
    int bid = blockIdx.x;
    int t = threadIdx.x;

    if (bid < POOLN) {
        // ---- prep (blocks 0..113), hidden under pool streaming ----
        if (bid < 114) {
            int idx = bid * 288 + t;
            if (idx < CC*CR) {
                int k = idx >> 6, o = idx & 63;
                float inv = bn_gamma[o] * rsqrtf(bn_var[o] + 1e-5f);
                g_w1t[idx] = w1[o * CC + k] * inv;
            }
            if (idx < CR*2*CC) {
                int k = idx >> 9, n = idx & 511;
                g_w2t[idx] = w2[n * CR + k];
            }
            if (idx < 2*9*CC) {
                int g = idx / (9*CC);
                int rem = idx - g * 9 * CC;
                int p = rem >> 8, c2 = rem & 255;
                g_dwt[idx] = dyn_weight[(g * CC + c2) * 9 + p];
            }
            if (idx < CR) {
                float inv = bn_gamma[idx] * rsqrtf(bn_var[idx] + 1e-5f);
                g_bnb[idx] = bn_beta[idx] - bn_mean[idx] * inv;
            }
            __threadfence();
            __syncthreads();
            if (t == 0) atomicAdd(&g_prep, 1u);
        }

        // ---- pooling: 9 warps, one 32x32 cell each ----
        int bc = bid;
        int b = bc >> 8, c = bc & 255;
        int w = t >> 5, lane = t & 31;
        int cy = w / 3, cx = w % 3;
        const float* base = x + (size_t)bc * (HH*WW) + cy * 32 * WW + cx * 32;
        float s = 0.f;
#pragma unroll
        for (int i = 0; i < 8; i++) {
            int f = lane + i * 32;
            int row = f >> 3, c4 = f & 7;
            float4 v = __ldcs(reinterpret_cast<const float4*>(base + row * WW + c4 * 4));
            s += v.x + v.y + v.z + v.w;
        }
#pragma unroll
        for (int o = 16; o; o >>= 1) s += __shfl_xor_sync(0xffffffffu, s, o);
        if (lane == 0) g_pooled[(b * 9 + w) * CC + c] = s;
        __threadfence();
        __syncthreads();
        if (t == 0) atomicAdd(&g_cnt[b], 1u);
        return;
    }

    // ---- proj block: positions pq and pq+5 for sample b ----
    int pid = bid - POOLN;
    int b = pid / 5, pq = pid % 5;

    if (t == 0) {
        unsigned R = atomicAdd(&g_pepoch, 1u) / PROJB;   // launch epoch
        while (atomicAdd(&g_prep, 0u) < 114u * (R + 1u)) __nanosleep(128);
        while (atomicAdd(&g_cnt[b], 0u) < 256u * (R + 1u)) __nanosleep(128);
        s_u = 1u;
    }
    __syncthreads();
    __threadfence();

    float* sv0 = scr;            // 256
    float* sv1 = scr + 256;      // 256
    float* pa  = scr + 512;      // 512
    float* sh0 = scr + 1024;     // 64
    float* sh1 = scr + 1088;     // 64
    int p = pq, p2 = pq + 5;

    if (t < CC) {
        float v0 = g_pooled[(b * 9 + p) * CC + t] * (1.0f / 1024.0f);
        float v1;
        if (p2 < 9) {
            v1 = g_pooled[(b * 9 + p2) * CC + t] * (1.0f / 1024.0f);
        } else {
            float s = 0.f;
#pragma unroll
            for (int q = 0; q < 9; q++) s += g_pooled[(b * 9 + q) * CC + t];
            v1 = s * (1.0f / (HH * WW));
        }
        sv0[t] = v0; sv1[t] = v1;
    }
    __syncthreads();

    if (t < 256) {
        int o = t & 63, slice = t >> 6;
        const float* w1s = g_w1t + slice * 64 * CR + o;
        const float* a0p = sv0 + slice * 64;
        const float* a1p = sv1 + slice * 64;
        float acc0 = 0.f, acc1 = 0.f;
#pragma unroll 8
        for (int k = 0; k < 64; k++) {
            float w = w1s[k * CR];
            acc0 = fmaf(w, a0p[k], acc0);
            acc1 = fmaf(w, a1p[k], acc1);
        }
        pa[t] = acc0; pa[256 + t] = acc1;
    }
    __syncthreads();

    if (t < 128) {
        int pos = t >> 6, oo = t & 63;
        const float* pp = pa + pos * 256;
        float h = pp[oo] + pp[oo + 64] + pp[oo + 128] + pp[oo + 192] + g_bnb[oo];
        h = 0.5f * h * (1.0f + erff(h * 0.70710678118654752f));
        if (pos) sh1[oo] = h; else sh0[oo] = h;
    }
    __syncthreads();

    if (t < CC) {
        int c = t;
        float a0 = b2[c], a1 = b2[CC + c];
        float d0 = a0, d1 = a1;
#pragma unroll 8
        for (int k = 0; k < CR; k++) {
            float w_0 = g_w2t[k * 512 + c];
            float w_1 = g_w2t[k * 512 + CC + c];
            float h0 = sh0[k], h1 = sh1[k];
            a0 = fmaf(w_0, h0, a0); a1 = fmaf(w_1, h0, a1);
            d0 = fmaf(w_0, h1, d0); d1 = fmaf(w_1, h1, d1);
        }
        {
            float m = fmaxf(a0, a1);
            float e0 = __expf(a0 - m), e1 = __expf(a1 - m);
            float r = 1.0f / (e0 + e1);
            g_weight[(b * 9 + p) * CC + c] = e0 * r * g_dwt[p * CC + c]
                                           + e1 * r * g_dwt[(9 + p) * CC + c];
        }
        {
            float m = fmaxf(d0, d1);
            float e0 = __expf(d0 - m), e1 = __expf(d1 - m);
            float r = 1.0f / (e0 + e1);
            if (p2 < 9) {
                g_weight[(b * 9 + p2) * CC + c] = e0 * r * g_dwt[p2 * CC + c]
                                                + e1 * r * g_dwt[(9 + p2) * CC + c];
            } else {
                g_bias[b * CC + c] = e0 * r * dyn_bias[c] + e1 * r * dyn_bias[CC + c];
            }
        }
    }
}

// ---------------------------------------------------------------------------
// Kernel 2: depthwise 3x3 conv + bias. Exact R8 kernel (wait-free, proven
// 93.7us @ 73% DRAM): PITCH=96, cp.async staging, 6 blocks/SM.
// ---------------------------------------------------------------------------
__global__ __launch_bounds__(288, 6) void dwconv_kernel(const float* __restrict__ x,
                                                        float* __restrict__ y) {
    __shared__ float tile[98 * PITCH];
    int bc = blockIdx.x;
    int t = threadIdx.x;
    const float* img = x + (size_t)bc * (HH*WW);
    float* outimg = y + (size_t)bc * (HH*WW);

    float4 z4 = make_float4(0.f,0.f,0.f,0.f);
    if (t < 24) {
        *reinterpret_cast<float4*>(&tile[t * 4]) = z4;
    } else if (t < 48) {
        *reinterpret_cast<float4*>(&tile[97 * PITCH + (t - 24) * 4]) = z4;
    }

#pragma unroll
    for (int i = 0; i < 8; i++) {
        int idx = t + i * 288;
        int r = idx / 24, j = idx % 24;
        unsigned sa = (unsigned)__cvta_generic_to_shared(&tile[(r + 1) * PITCH + j * 4]);
        asm volatile("cp.async.cg.shared.global [%0], [%1], 16;\n"
                     :: "r"(sa), "l"(img + r * WW + j * 4));
    }
    asm volatile("cp.async.commit_group;\n");
    asm volatile("cp.async.wait_group 0;\n");
    __syncthreads();

    int b = bc >> 8, c = bc & 255;
    float w0 = g_weight[(b*9+0)*CC+c], w1_ = g_weight[(b*9+1)*CC+c], w2_ = g_weight[(b*9+2)*CC+c];
    float w3 = g_weight[(b*9+3)*CC+c], w4  = g_weight[(b*9+4)*CC+c], w5  = g_weight[(b*9+5)*CC+c];
    float w6 = g_weight[(b*9+6)*CC+c], w7  = g_weight[(b*9+7)*CC+c], w8  = g_weight[(b*9+8)*CC+c];
    float bv = g_bias[bc];

    int tx = t % 24;
    int ty = t / 24;
    int x0 = tx * 4;
    int r0 = ty * 8;
    bool hasL = (tx > 0), hasR = (tx < 23);

    float4 aA = make_float4(0.f,0.f,0.f,0.f);
    float4 aB = make_float4(0.f,0.f,0.f,0.f);
    float4 aC = make_float4(0.f,0.f,0.f,0.f);

#pragma unroll
    for (int s = 0; s < 10; ++s) {
        const float* row = &tile[(r0 + s) * PITCH + x0];
        float4 v = *reinterpret_cast<const float4*>(row);
        float l  = hasL ? row[-1] : 0.f;
        float rr = hasR ? row[4]  : 0.f;
        float c0 = v.x, c1 = v.y, c2 = v.z, c3 = v.w;

        aA.x = fmaf(l,  w6, fmaf(c0, w7, fmaf(c1, w8, aA.x)));
        aA.y = fmaf(c0, w6, fmaf(c1, w7, fmaf(c2, w8, aA.y)));
        aA.z = fmaf(c1, w6, fmaf(c2, w7, fmaf(c3, w8, aA.z)));
        aA.w = fmaf(c2, w6, fmaf(c3, w7, fmaf(rr, w8, aA.w)));

        aB.x = fmaf(l,  w3, fmaf(c0, w4, fmaf(c1, w5, aB.x)));
        aB.y = fmaf(c0, w3, fmaf(c1, w4, fmaf(c2, w5, aB.y)));
        aB.z = fmaf(c1, w3, fmaf(c2, w4, fmaf(c3, w5, aB.z)));
        aB.w = fmaf(c2, w3, fmaf(c3, w4, fmaf(rr, w5, aB.w)));

        aC.x = fmaf(l,  w0, fmaf(c0, w1_, fmaf(c1, w2_, aC.x)));
        aC.y = fmaf(c0, w0, fmaf(c1, w1_, fmaf(c2, w2_, aC.y)));
        aC.z = fmaf(c1, w0, fmaf(c2, w1_, fmaf(c3, w2_, aC.z)));
        aC.w = fmaf(c2, w0, fmaf(c3, w1_, fmaf(rr, w2_, aC.w)));

        if (s >= 2) {
            int yo = r0 + s - 2;
            float4 o;
            o.x = aA.x + bv; o.y = aA.y + bv; o.z = aA.z + bv; o.w = aA.w + bv;
            __stcs(reinterpret_cast<float4*>(outimg + yo * WW + x0), o);
        }
        aA = aB; aB = aC;
        aC = make_float4(0.f,0.f,0.f,0.f);
    }
}

extern "C" void kernel_launch(void* const* d_in, const int* in_sizes, int n_in,
                              void* d_out, int out_size) {
    const float* x          = (const float*)d_in[0];
    const float* dyn_weight = (const float*)d_in[1];
    const float* dyn_bias   = (const float*)d_in[2];
    const float* w1         = (const float*)d_in[3];
    const float* bn_gamma   = (const float*)d_in[4];
    const float* bn_beta    = (const float*)d_in[5];
    const float* bn_mean    = (const float*)d_in[6];
    const float* bn_var     = (const float*)d_in[7];
    const float* w2         = (const float*)d_in[8];
    const float* b2         = (const float*)d_in[9];
    float* out = (float*)d_out;

    pool_proj_kernel<<<POOLN + PROJB, 288>>>(x, dyn_weight, dyn_bias, w1,
                                             bn_gamma, bn_beta, bn_mean, bn_var,
                                             w2, b2);
    dwconv_kernel<<<POOLN, 288>>>(x, out);
}